// round 4
// baseline (speedup 1.0000x reference)
#include <cuda_runtime.h>
#include <math.h>

// Problem constants
#define Bv 8
#define Sv 4096
#define Ev 512
#define Hv 8
#define Dv 64
#define Mv (Bv * Sv)          // 32768 rows
#define EPSv 1e-6f

// ---------------------------------------------------------------------------
// Scratch (device globals: allocation-free rule)
// ---------------------------------------------------------------------------
__device__ float g_q[(size_t)Mv * Ev];      // feature_map(q)  [B*S, H*D]
__device__ float g_k[(size_t)Mv * Ev];      // feature_map(k)
__device__ float g_v[(size_t)Mv * Ev];      // v
__device__ float g_attn[(size_t)Mv * Ev];   // pre-output-proj attention result
__device__ float g_kv[Bv * Hv * Dv * Dv];   // KV[bh][d][m] = sum_s k[d]*v[m]
__device__ float g_ksum[Bv * Hv * Dv];      // sum_s k[d]

// ---------------------------------------------------------------------------
// Kernel 0: zero the accumulators (must run every launch; graph replays)
// ---------------------------------------------------------------------------
__global__ void zero_acc_kernel() {
    int i = blockIdx.x * blockDim.x + threadIdx.x;
    if (i < Bv * Hv * Dv * Dv) g_kv[i] = 0.0f;
    if (i < Bv * Hv * Dv)      g_ksum[i] = 0.0f;
}

// ---------------------------------------------------------------------------
// Kernel 1/4: SGEMM  C[M,N] = A[M,K] @ W[K,N] + bias[N]  (+ optional elu+1)
// 128x128 block tile, K-tile 16, 256 threads, 8x8 per-thread micro-tile.
// ---------------------------------------------------------------------------
template <int ACT>
__global__ __launch_bounds__(256)
void gemm_kernel(const float* __restrict__ A, const float* __restrict__ W,
                 const float* __restrict__ bias, float* __restrict__ C,
                 int M, int N, int K)
{
    __shared__ float As[16][128];   // As[k][m] (transposed on load)
    __shared__ float Bs[16][128];   // Bs[k][n]

    const int tid   = threadIdx.x;
    const int m_blk = blockIdx.y * 128;
    const int n_blk = blockIdx.x * 128;
    const int ty = tid >> 4, tx = tid & 15;
    const int m0 = ty * 8, n0 = tx * 8;

    float acc[8][8];
#pragma unroll
    for (int i = 0; i < 8; i++)
#pragma unroll
        for (int j = 0; j < 8; j++) acc[i][j] = 0.0f;

    for (int kt = 0; kt < K; kt += 16) {
        // A tile: 128 rows x 16 cols = 512 float4 slots
#pragma unroll
        for (int s = 0; s < 2; s++) {
            int slot = tid + s * 256;
            int r  = slot >> 2;          // 0..127
            int c4 = (slot & 3) * 4;     // 0,4,8,12
            float4 av = *(const float4*)(A + (size_t)(m_blk + r) * K + kt + c4);
            As[c4 + 0][r] = av.x;
            As[c4 + 1][r] = av.y;
            As[c4 + 2][r] = av.z;
            As[c4 + 3][r] = av.w;
        }
        // B tile: 16 rows x 128 cols = 512 float4 slots
#pragma unroll
        for (int s = 0; s < 2; s++) {
            int slot = tid + s * 256;
            int r  = slot >> 5;          // 0..15
            int c4 = (slot & 31) * 4;    // 0..124
            *(float4*)&Bs[r][c4] =
                *(const float4*)(W + (size_t)(kt + r) * N + n_blk + c4);
        }
        __syncthreads();

#pragma unroll
        for (int k = 0; k < 16; k++) {
            float a[8], b[8];
            *(float4*)&a[0] = *(float4*)&As[k][m0];
            *(float4*)&a[4] = *(float4*)&As[k][m0 + 4];
            *(float4*)&b[0] = *(float4*)&Bs[k][n0];
            *(float4*)&b[4] = *(float4*)&Bs[k][n0 + 4];
#pragma unroll
            for (int i = 0; i < 8; i++)
#pragma unroll
                for (int j = 0; j < 8; j++)
                    acc[i][j] = fmaf(a[i], b[j], acc[i][j]);
        }
        __syncthreads();
    }

    // Epilogue: bias (+ feature map)
    float bl[8];
    *(float4*)&bl[0] = *(const float4*)(bias + n_blk + n0);
    *(float4*)&bl[4] = *(const float4*)(bias + n_blk + n0 + 4);
#pragma unroll
    for (int i = 0; i < 8; i++) {
        float out[8];
#pragma unroll
        for (int j = 0; j < 8; j++) {
            float x = acc[i][j] + bl[j];
            if (ACT) x = (x > 0.0f) ? (x + 1.0f) : expf(x);  // elu(x)+1
            out[j] = x;
        }
        float* cp = C + (size_t)(m_blk + m0 + i) * N + n_blk + n0;
        *(float4*)cp       = *(float4*)&out[0];
        *(float4*)(cp + 4) = *(float4*)&out[4];
    }
}

// ---------------------------------------------------------------------------
// Kernel 2: per (b,h) KV = sum_s k_s (outer) v_s  and ksum = sum_s k_s
// grid = (8 S-splits, 64 bh). 256 threads as 16(d-groups) x 16(m-groups),
// each thread owns a 4x4 scatter of the 64x64 KV matrix.
// ---------------------------------------------------------------------------
__global__ __launch_bounds__(256)
void kvsum_kernel() {
    __shared__ float ks[32][64];
    __shared__ float vs[32][64];

    const int tid   = threadIdx.x;
    const int split = blockIdx.x;   // 0..7
    const int bh    = blockIdx.y;   // 0..63
    const int b = bh >> 3, h = bh & 7;
    const int ty = tid >> 4, tx = tid & 15;

    float acc[4][4];
    float ksa[4];
#pragma unroll
    for (int u = 0; u < 4; u++) {
        ksa[u] = 0.0f;
#pragma unroll
        for (int w = 0; w < 4; w++) acc[u][w] = 0.0f;
    }

    const int s_base = split * (Sv / 8);   // 512 rows per block

    for (int chunk = 0; chunk < 16; chunk++) {
        int s0 = s_base + chunk * 32;
        // stage 32 rows x 64 cols of k and v: 512 float4 slots each
#pragma unroll
        for (int s = 0; s < 2; s++) {
            int slot = tid + s * 256;
            int r  = slot >> 4;          // 0..31
            int c4 = (slot & 15) * 4;    // 0..60
            size_t gidx = ((size_t)(b * Sv + s0 + r) * Hv + h) * Dv + c4;
            *(float4*)&ks[r][c4] = *(const float4*)(g_k + gidx);
            *(float4*)&vs[r][c4] = *(const float4*)(g_v + gidx);
        }
        __syncthreads();

        for (int sp = 0; sp < 32; sp++) {
            float kr[4], vr[4];
#pragma unroll
            for (int u = 0; u < 4; u++) kr[u] = ks[sp][ty + 16 * u];
#pragma unroll
            for (int u = 0; u < 4; u++) vr[u] = vs[sp][tx + 16 * u];
#pragma unroll
            for (int u = 0; u < 4; u++)
#pragma unroll
                for (int w = 0; w < 4; w++)
                    acc[u][w] = fmaf(kr[u], vr[w], acc[u][w]);
            if (tx == 0) {
#pragma unroll
                for (int u = 0; u < 4; u++) ksa[u] += kr[u];
            }
        }
        __syncthreads();
    }

#pragma unroll
    for (int u = 0; u < 4; u++)
#pragma unroll
        for (int w = 0; w < 4; w++)
            atomicAdd(&g_kv[(size_t)bh * Dv * Dv + (ty + 16 * u) * Dv + (tx + 16 * w)],
                      acc[u][w]);
    if (tx == 0) {
#pragma unroll
        for (int u = 0; u < 4; u++)
            atomicAdd(&g_ksum[bh * Dv + ty + 16 * u], ksa[u]);
    }
}

// ---------------------------------------------------------------------------
// Kernel 3: attention apply. Per (b,h): out[s,:] = (q[s,:] @ KV) * z(s)
// with z(s) = 1/(q[s,:]·ksum + eps). Tile: 128 rows x 64 cols, K=64.
// The z-dot is fused into the main k-loop (reuses the loaded q fragment).
// ---------------------------------------------------------------------------
__global__ __launch_bounds__(256)
void attn_kernel() {
    __shared__ float qs[128][64];   // 32 KB
    __shared__ float kvs[64][64];   // 16 KB  (kvs[d][m])

    const int tid = threadIdx.x;
    const int bh  = blockIdx.x;     // 0..63
    const int b = bh >> 3, h = bh & 7;
    const int s0 = blockIdx.y * 128;

    // Load KV (contiguous 4096 floats)
#pragma unroll
    for (int s = 0; s < 4; s++) {
        int slot = tid + s * 256;
        *(float4*)((float*)kvs + slot * 4) =
            *(const float4*)(g_kv + (size_t)bh * Dv * Dv + slot * 4);
    }
    // Load q tile 128x64
#pragma unroll
    for (int s = 0; s < 8; s++) {
        int slot = tid + s * 256;
        int r  = slot >> 4;          // 0..127
        int c4 = (slot & 15) * 4;
        *(float4*)&qs[r][c4] =
            *(const float4*)(g_q + ((size_t)(b * Sv + s0 + r) * Hv + h) * Dv + c4);
    }
    __syncthreads();

    const int ty = tid >> 4, tx = tid & 15;
    const int m0 = ty * 8, n0 = tx * 4;

    float acc[8][4];
    float zacc[8];
#pragma unroll
    for (int i = 0; i < 8; i++) {
        zacc[i] = 0.0f;
#pragma unroll
        for (int j = 0; j < 4; j++) acc[i][j] = 0.0f;
    }

    const float* ksp = g_ksum + bh * Dv;

#pragma unroll 4
    for (int k = 0; k < 64; k++) {
        float bfr[4];
        *(float4*)bfr = *(float4*)&kvs[k][n0];
        float ksv = __ldg(ksp + k);   // uniform, L1-resident
#pragma unroll
        for (int i = 0; i < 8; i++) {
            float a = qs[m0 + i][k];
            zacc[i] = fmaf(a, ksv, zacc[i]);
#pragma unroll
            for (int j = 0; j < 4; j++)
                acc[i][j] = fmaf(a, bfr[j], acc[i][j]);
        }
    }

#pragma unroll
    for (int i = 0; i < 8; i++) {
        float z = 1.0f / (zacc[i] + EPSv);
        float out[4];
#pragma unroll
        for (int j = 0; j < 4; j++) out[j] = acc[i][j] * z;
        *(float4*)(g_attn + ((size_t)(b * Sv + s0 + m0 + i) * Hv + h) * Dv + n0) =
            *(float4*)&out[0];
    }
}

// ---------------------------------------------------------------------------
// Launch
// ---------------------------------------------------------------------------
extern "C" void kernel_launch(void* const* d_in, const int* in_sizes, int n_in,
                              void* d_out, int out_size)
{
    const float* x  = (const float*)d_in[0];
    const float* Wq = (const float*)d_in[1];
    const float* bq = (const float*)d_in[2];
    const float* Wk = (const float*)d_in[3];
    const float* bk = (const float*)d_in[4];
    const float* Wv = (const float*)d_in[5];
    const float* bv = (const float*)d_in[6];
    const float* Wo = (const float*)d_in[7];
    const float* bo = (const float*)d_in[8];
    float* out = (float*)d_out;

    // Resolve scratch addresses (host-side query; capture-safe, no stream ops)
    float *qp, *kp, *vp, *ap;
    cudaGetSymbolAddress((void**)&qp, g_q);
    cudaGetSymbolAddress((void**)&kp, g_k);
    cudaGetSymbolAddress((void**)&vp, g_v);
    cudaGetSymbolAddress((void**)&ap, g_attn);

    // 0) zero KV/ksum accumulators (needed on every graph replay)
    zero_acc_kernel<<<(Bv * Hv * Dv * Dv + 255) / 256, 256>>>();

    // 1) projections (feature map fused into q,k epilogues)
    dim3 gg(Ev / 128, Mv / 128);   // (4, 256)
    gemm_kernel<1><<<gg, 256>>>(x, Wq, bq, qp, Mv, Ev, Ev);
    gemm_kernel<1><<<gg, 256>>>(x, Wk, bk, kp, Mv, Ev, Ev);
    gemm_kernel<0><<<gg, 256>>>(x, Wv, bv, vp, Mv, Ev, Ev);

    // 2) KV outer-product reduction + ksum (split-S x8, atomics)
    kvsum_kernel<<<dim3(8, Bv * Hv), 256>>>();

    // 3) attention apply (q @ KV with fused normalizer)
    attn_kernel<<<dim3(Bv * Hv, Sv / 128), 256>>>();

    // 4) output projection -> d_out
    gemm_kernel<0><<<gg, 256>>>(ap, Wo, bo, out, Mv, Ev, Ev);
}

// round 8
// speedup vs baseline: 2.1895x; 2.1895x over previous
#include <cuda_runtime.h>
#include <cuda_bf16.h>
#include <math.h>
#include <stdint.h>

// Problem constants
#define Bv 8
#define Sv 4096
#define Ev 512
#define Hv 8
#define Dv 64
#define Mv (Bv * Sv)          // 32768 rows
#define EPSv 1e-6f

// GEMM tiling: 128(M) x 128(N) tiles, K-chunk 64 (bf16), K=512 -> 8 chunks
#define TILE_BYTES 16384              // 128 rows x 64 bf16 (128B rows, swizzled)
#define STAGE_BYTES (4 * TILE_BYTES)  // Ahi, Alo, Bhi, Blo
#define NCHUNK 8
#define SMEM_GEMM (2 * STAGE_BYTES + 1024)   // 2 stages + alignment slack

// ---------------------------------------------------------------------------
// Scratch (device globals: allocation-free rule)
// ---------------------------------------------------------------------------
__device__ float g_q[(size_t)Mv * Ev];
__device__ float g_k[(size_t)Mv * Ev];
__device__ float g_v[(size_t)Mv * Ev];
__device__ float g_kv[Bv * Hv * Dv * Dv];
__device__ float g_ksum[Bv * Hv * Dv];

// Packed SW128-swizzled bf16 tiles: [mtile(256)][kchunk(8)][16384B]
__device__ __align__(1024) unsigned char g_xt_hi[(size_t)Mv * Ev * 2];
__device__ __align__(1024) unsigned char g_xt_lo[(size_t)Mv * Ev * 2];
__device__ __align__(1024) unsigned char g_at_hi[(size_t)Mv * Ev * 2];
__device__ __align__(1024) unsigned char g_at_lo[(size_t)Mv * Ev * 2];
// Weights, transposed+packed: [ntile(4)][kchunk(8)][16384B] per weight
__device__ __align__(1024) unsigned char g_w_hi[4][(size_t)Ev * Ev * 2];
__device__ __align__(1024) unsigned char g_w_lo[4][(size_t)Ev * Ev * 2];

// ---------------------------------------------------------------------------
// Helpers (baseline PTX only: sm_80/sm_90 features, no 'a'-suffix ISA)
// ---------------------------------------------------------------------------
__device__ __forceinline__ uint32_t smem_u32(const void* p) {
    uint32_t a;
    asm("{ .reg .u64 t; cvta.to.shared.u64 t, %1; cvt.u32.u64 %0, t; }"
        : "=r"(a) : "l"(p));
    return a;
}

__device__ __forceinline__ void cp16(uint32_t dst, const void* src) {
    asm volatile("cp.async.cg.shared.global [%0], [%1], 16;"
                 :: "r"(dst), "l"(src) : "memory");
}
#define CP_COMMIT() asm volatile("cp.async.commit_group;" ::: "memory")
#define CP_WAIT1()  asm volatile("cp.async.wait_group 1;" ::: "memory")
#define CP_WAIT0()  asm volatile("cp.async.wait_group 0;" ::: "memory")

__device__ __forceinline__ void ldsm_x4(uint32_t* r, uint32_t addr) {
    asm volatile("ldmatrix.sync.aligned.m8n8.x4.shared.b16 {%0,%1,%2,%3}, [%4];"
                 : "=r"(r[0]), "=r"(r[1]), "=r"(r[2]), "=r"(r[3]) : "r"(addr));
}

// D += A(bf16) * B(bf16), m16n8k16, A row-major, B col-major
__device__ __forceinline__ void mma16816(float* d, const uint32_t* a, const uint32_t* b) {
    asm volatile(
        "mma.sync.aligned.m16n8k16.row.col.f32.bf16.bf16.f32 "
        "{%0,%1,%2,%3}, {%4,%5,%6,%7}, {%8,%9}, {%0,%1,%2,%3};"
        : "+f"(d[0]), "+f"(d[1]), "+f"(d[2]), "+f"(d[3])
        : "r"(a[0]), "r"(a[1]), "r"(a[2]), "r"(a[3]), "r"(b[0]), "r"(b[1]));
}

__device__ __forceinline__ uint32_t sw128(uint32_t off) {
    return off ^ ((off >> 3) & 0x70);
}
__device__ __forceinline__ uint32_t pack_bf16x2(__nv_bfloat16 a, __nv_bfloat16 b) {
    return (uint32_t)__bfloat16_as_ushort(a) | ((uint32_t)__bfloat16_as_ushort(b) << 16);
}

// ---------------------------------------------------------------------------
// Kernel 0: zero the accumulators (graph replays)
// ---------------------------------------------------------------------------
__global__ void zero_acc_kernel() {
    int i = blockIdx.x * blockDim.x + threadIdx.x;
    if (i < Bv * Hv * Dv * Dv) g_kv[i] = 0.0f;
    if (i < Bv * Hv * Dv)      g_ksum[i] = 0.0f;
}

// ---------------------------------------------------------------------------
// packA: fp32 [M,512] row-major -> SW128-swizzled bf16 hi/lo tiles
// ---------------------------------------------------------------------------
__global__ __launch_bounds__(256)
void packA_kernel(const float* __restrict__ X,
                  unsigned char* __restrict__ hiT, unsigned char* __restrict__ loT)
{
    __shared__ unsigned char sh[TILE_BYTES];
    __shared__ unsigned char sl[TILE_BYTES];
    const int tid = threadIdx.x;
    const int kc = blockIdx.x, mt = blockIdx.y;
    const int kt = kc * 64;
    const size_t mbase = (size_t)mt * 128;
#pragma unroll
    for (int i = 0; i < 8; i++) {
        int slot = tid + i * 256;            // 0..2047
        int r  = slot >> 4;                  // 0..127
        int c4 = (slot & 15) << 2;           // 0..60
        float4 xv = *(const float4*)(X + (mbase + r) * Ev + kt + c4);
        float xa[4] = {xv.x, xv.y, xv.z, xv.w};
        __nv_bfloat16 h[4], l[4];
#pragma unroll
        for (int j = 0; j < 4; j++) {
            h[j] = __float2bfloat16(xa[j]);
            l[j] = __float2bfloat16(xa[j] - __bfloat162float(h[j]));
        }
        uint32_t sw = sw128((uint32_t)(r * 128 + c4 * 2));
        uint2 hv = {pack_bf16x2(h[0], h[1]), pack_bf16x2(h[2], h[3])};
        uint2 lv = {pack_bf16x2(l[0], l[1]), pack_bf16x2(l[2], l[3])};
        *(uint2*)(sh + sw) = hv;
        *(uint2*)(sl + sw) = lv;
    }
    __syncthreads();
    size_t toff = ((size_t)mt * NCHUNK + kc) * TILE_BYTES;
#pragma unroll
    for (int i = 0; i < 4; i++) {
        int slot = tid + i * 256;
        *(uint4*)(hiT + toff + slot * 16) = *(uint4*)(sh + slot * 16);
        *(uint4*)(loT + toff + slot * 16) = *(uint4*)(sl + slot * 16);
    }
}

// ---------------------------------------------------------------------------
// packB: W [K=512][N=512] fp32 -> transposed swizzled tiles [ntile][kchunk]
// stored as B[n][k] with k contiguous (col-major B for mma.row.col)
// ---------------------------------------------------------------------------
__global__ __launch_bounds__(256)
void packB_kernel(const float* __restrict__ W,
                  unsigned char* __restrict__ hiT, unsigned char* __restrict__ loT)
{
    __shared__ unsigned char sh[TILE_BYTES];
    __shared__ unsigned char sl[TILE_BYTES];
    const int tid = threadIdx.x;
    const int kc = blockIdx.x, nt = blockIdx.y;
    const int kt = kc * 64, n0 = nt * 128;
#pragma unroll
    for (int i = 0; i < 8; i++) {
        int slot = tid + i * 256;            // 0..2047
        int r  = slot >> 5;                  // 0..63  (k within chunk)
        int c4 = (slot & 31) << 2;           // 0..124 (n within tile)
        float4 wv = *(const float4*)(W + (size_t)(kt + r) * Ev + n0 + c4);
        float wa[4] = {wv.x, wv.y, wv.z, wv.w};
#pragma unroll
        for (int j = 0; j < 4; j++) {
            uint32_t sw = sw128((uint32_t)((c4 + j) * 128 + r * 2));
            __nv_bfloat16 h = __float2bfloat16(wa[j]);
            __nv_bfloat16 l = __float2bfloat16(wa[j] - __bfloat162float(h));
            *(unsigned short*)(sh + sw) = __bfloat16_as_ushort(h);
            *(unsigned short*)(sl + sw) = __bfloat16_as_ushort(l);
        }
    }
    __syncthreads();
    size_t toff = ((size_t)nt * NCHUNK + kc) * TILE_BYTES;
#pragma unroll
    for (int i = 0; i < 4; i++) {
        int slot = tid + i * 256;
        *(uint4*)(hiT + toff + slot * 16) = *(uint4*)(sh + slot * 16);
        *(uint4*)(loT + toff + slot * 16) = *(uint4*)(sl + slot * 16);
    }
}

// ---------------------------------------------------------------------------
// mma.sync GEMM: C[M,512] = A @ B^T + bias (+ optional elu+1)
// 3-term bf16 split: Ah*Bh + Ah*Bl + Al*Bh with fp32 accumulation.
// 256 threads = 8 warps (4 along m, 2 along n); warp tile 32x64.
// 2-stage cp.async double buffer.
// ---------------------------------------------------------------------------
__device__ __forceinline__ void copy_stage(uint32_t sdst,
    const unsigned char* ah, const unsigned char* al,
    const unsigned char* bh, const unsigned char* bl, int tid)
{
#pragma unroll
    for (int i = 0; i < 4; i++) {
        int off = (tid + i * 256) * 16;
        cp16(sdst + off,                     ah + off);
        cp16(sdst + TILE_BYTES + off,        al + off);
        cp16(sdst + 2 * TILE_BYTES + off,    bh + off);
        cp16(sdst + 3 * TILE_BYTES + off,    bl + off);
    }
    CP_COMMIT();
}

template <int ACT>
__global__ __launch_bounds__(256)
void gemm_mma_kernel(const unsigned char* __restrict__ Ahi,
                     const unsigned char* __restrict__ Alo,
                     const unsigned char* __restrict__ Bhi,
                     const unsigned char* __restrict__ Blo,
                     const float* __restrict__ bias, float* __restrict__ C)
{
    extern __shared__ unsigned char smem_raw[];
    const uint32_t sb = (smem_u32(smem_raw) + 1023u) & ~1023u;

    const int tid  = threadIdx.x;
    const int lane = tid & 31, wid = tid >> 5;
    const int nt = blockIdx.x;   // 0..3
    const int mt = blockIdx.y;   // 0..255
    const int wm = wid & 3;      // m warp: 0..3  (32 rows each)
    const int wn = wid >> 2;     // n warp: 0..1  (64 cols each)

    const unsigned char* ah = Ahi + (size_t)mt * NCHUNK * TILE_BYTES;
    const unsigned char* al = Alo + (size_t)mt * NCHUNK * TILE_BYTES;
    const unsigned char* bh = Bhi + (size_t)nt * NCHUNK * TILE_BYTES;
    const unsigned char* bl = Blo + (size_t)nt * NCHUNK * TILE_BYTES;

    // Prologue: prefetch chunks 0 and 1
    copy_stage(sb,               ah, al, bh, bl, tid);
    copy_stage(sb + STAGE_BYTES, ah + TILE_BYTES, al + TILE_BYTES,
               bh + TILE_BYTES, bl + TILE_BYTES, tid);

    float acc[2][8][4];
#pragma unroll
    for (int mf = 0; mf < 2; mf++)
#pragma unroll
        for (int nf = 0; nf < 8; nf++)
#pragma unroll
            for (int j = 0; j < 4; j++) acc[mf][nf][j] = 0.0f;

    // Precompute lane-dependent ldmatrix offset components
    const int a_row  = wm * 32 + (lane & 7) + ((lane >> 3) & 1) * 8;  // + mf*16
    const int a_colb = ((lane >> 4) & 1) * 16;                        // + ks*32
    const int b_row  = wn * 64 + (lane & 7) + ((lane >> 4) & 1) * 8;  // + nfp*16
    const int b_colb = ((lane >> 3) & 1) * 16;                        // + ks*32

    for (int t = 0; t < NCHUNK; t++) {
        if (t == NCHUNK - 1) { CP_WAIT0(); } else { CP_WAIT1(); }
        __syncthreads();
        const uint32_t st = sb + (uint32_t)(t & 1) * STAGE_BYTES;

#pragma unroll
        for (int ks = 0; ks < 4; ks++) {
            uint32_t ahf[2][4], alf[2][4];
#pragma unroll
            for (int mf = 0; mf < 2; mf++) {
                uint32_t off = sw128((uint32_t)((a_row + mf * 16) * 128 + a_colb + ks * 32));
                ldsm_x4(ahf[mf], st + off);
                ldsm_x4(alf[mf], st + TILE_BYTES + off);
            }
#pragma unroll
            for (int nfp = 0; nfp < 4; nfp++) {
                uint32_t off = sw128((uint32_t)((b_row + nfp * 16) * 128 + b_colb + ks * 32));
                uint32_t bh4[4], bl4[4];
                ldsm_x4(bh4, st + 2 * TILE_BYTES + off);
                ldsm_x4(bl4, st + 3 * TILE_BYTES + off);
                const int ne = nfp * 2, no = nfp * 2 + 1;
                // term 1: Ah*Bh
                mma16816(acc[0][ne], ahf[0], bh4);     mma16816(acc[0][no], ahf[0], bh4 + 2);
                mma16816(acc[1][ne], ahf[1], bh4);     mma16816(acc[1][no], ahf[1], bh4 + 2);
                // term 2: Ah*Bl
                mma16816(acc[0][ne], ahf[0], bl4);     mma16816(acc[0][no], ahf[0], bl4 + 2);
                mma16816(acc[1][ne], ahf[1], bl4);     mma16816(acc[1][no], ahf[1], bl4 + 2);
                // term 3: Al*Bh
                mma16816(acc[0][ne], alf[0], bh4);     mma16816(acc[0][no], alf[0], bh4 + 2);
                mma16816(acc[1][ne], alf[1], bh4);     mma16816(acc[1][no], alf[1], bh4 + 2);
            }
        }
        __syncthreads();
        if (t + 2 < NCHUNK) {
            size_t coff = (size_t)(t + 2) * TILE_BYTES;
            copy_stage(st, ah + coff, al + coff, bh + coff, bl + coff, tid);
        }
    }

    // Epilogue: fragment (mf, nf): rows = mt*128+wm*32+mf*16+lane/4 (+8),
    // cols = nt*128+wn*64+nf*8+(lane%4)*2
    const int row_base = mt * 128 + wm * 32 + (lane >> 2);
    const int col_base = nt * 128 + wn * 64 + (lane & 3) * 2;
#pragma unroll
    for (int mf = 0; mf < 2; mf++) {
#pragma unroll
        for (int nf = 0; nf < 8; nf++) {
            int col = col_base + nf * 8;
            float b0 = __ldg(bias + col), b1 = __ldg(bias + col + 1);
#pragma unroll
            for (int half = 0; half < 2; half++) {
                int row = row_base + mf * 16 + half * 8;
                float x0 = acc[mf][nf][half * 2 + 0] + b0;
                float x1 = acc[mf][nf][half * 2 + 1] + b1;
                if (ACT) {
                    x0 = (x0 > 0.0f) ? (x0 + 1.0f) : expf(x0);
                    x1 = (x1 > 0.0f) ? (x1 + 1.0f) : expf(x1);
                }
                float2 v = make_float2(x0, x1);
                *(float2*)(C + (size_t)row * Ev + col) = v;
            }
        }
    }
}

// ---------------------------------------------------------------------------
// kvsum: per (b,h) KV = sum_s k (outer) v, ksum = sum_s k
// ---------------------------------------------------------------------------
__global__ __launch_bounds__(256)
void kvsum_kernel() {
    __shared__ float ks[32][64];
    __shared__ float vs[32][64];

    const int tid   = threadIdx.x;
    const int split = blockIdx.x;
    const int bh    = blockIdx.y;
    const int b = bh >> 3, h = bh & 7;
    const int ty = tid >> 4, tx = tid & 15;

    float acc[4][4];
    float ksa[4];
#pragma unroll
    for (int u = 0; u < 4; u++) {
        ksa[u] = 0.0f;
#pragma unroll
        for (int w = 0; w < 4; w++) acc[u][w] = 0.0f;
    }

    const int s_base = split * (Sv / 8);
    for (int chunk = 0; chunk < 16; chunk++) {
        int s0 = s_base + chunk * 32;
#pragma unroll
        for (int s = 0; s < 2; s++) {
            int slot = tid + s * 256;
            int r  = slot >> 4;
            int c4 = (slot & 15) * 4;
            size_t gidx = ((size_t)(b * Sv + s0 + r) * Hv + h) * Dv + c4;
            *(float4*)&ks[r][c4] = *(const float4*)(g_k + gidx);
            *(float4*)&vs[r][c4] = *(const float4*)(g_v + gidx);
        }
        __syncthreads();

        for (int sp = 0; sp < 32; sp++) {
            float kr[4], vr[4];
#pragma unroll
            for (int u = 0; u < 4; u++) kr[u] = ks[sp][ty + 16 * u];
#pragma unroll
            for (int u = 0; u < 4; u++) vr[u] = vs[sp][tx + 16 * u];
#pragma unroll
            for (int u = 0; u < 4; u++)
#pragma unroll
                for (int w = 0; w < 4; w++)
                    acc[u][w] = fmaf(kr[u], vr[w], acc[u][w]);
            if (tx == 0) {
#pragma unroll
                for (int u = 0; u < 4; u++) ksa[u] += kr[u];
            }
        }
        __syncthreads();
    }

#pragma unroll
    for (int u = 0; u < 4; u++)
#pragma unroll
        for (int w = 0; w < 4; w++)
            atomicAdd(&g_kv[(size_t)bh * Dv * Dv + (ty + 16 * u) * Dv + (tx + 16 * w)],
                      acc[u][w]);
    if (tx == 0) {
#pragma unroll
        for (int u = 0; u < 4; u++)
            atomicAdd(&g_ksum[bh * Dv + ty + 16 * u], ksa[u]);
    }
}

// ---------------------------------------------------------------------------
// attn apply: out = (q @ KV) * z, written DIRECTLY as packed bf16 hi/lo tiles
// ---------------------------------------------------------------------------
__global__ __launch_bounds__(256)
void attn_kernel() {
    __shared__ float qs[128][64];
    __shared__ float kvs[64][64];

    const int tid = threadIdx.x;
    const int bh  = blockIdx.x;
    const int b = bh >> 3, h = bh & 7;
    const int st = blockIdx.y;
    const int s0 = st * 128;

#pragma unroll
    for (int s = 0; s < 4; s++) {
        int slot = tid + s * 256;
        *(float4*)((float*)kvs + slot * 4) =
            *(const float4*)(g_kv + (size_t)bh * Dv * Dv + slot * 4);
    }
#pragma unroll
    for (int s = 0; s < 8; s++) {
        int slot = tid + s * 256;
        int r  = slot >> 4;
        int c4 = (slot & 15) * 4;
        *(float4*)&qs[r][c4] =
            *(const float4*)(g_q + ((size_t)(b * Sv + s0 + r) * Hv + h) * Dv + c4);
    }
    __syncthreads();

    const int ty = tid >> 4, tx = tid & 15;
    const int m0 = ty * 8, n0 = tx * 4;

    float acc[8][4];
    float zacc[8];
#pragma unroll
    for (int i = 0; i < 8; i++) {
        zacc[i] = 0.0f;
#pragma unroll
        for (int j = 0; j < 4; j++) acc[i][j] = 0.0f;
    }

    const float* ksp = g_ksum + bh * Dv;
#pragma unroll 4
    for (int k = 0; k < 64; k++) {
        float bfr[4];
        *(float4*)bfr = *(float4*)&kvs[k][n0];
        float ksv = __ldg(ksp + k);
#pragma unroll
        for (int i = 0; i < 8; i++) {
            float a = qs[m0 + i][k];
            zacc[i] = fmaf(a, ksv, zacc[i]);
#pragma unroll
            for (int j = 0; j < 4; j++)
                acc[i][j] = fmaf(a, bfr[j], acc[i][j]);
        }
    }

    // Emit packed swizzled bf16 hi/lo tile (tile = (b*32+st, kchunk h))
    const size_t toff = ((size_t)(b * 32 + st) * NCHUNK + h) * TILE_BYTES;
#pragma unroll
    for (int i = 0; i < 8; i++) {
        float z = 1.0f / (zacc[i] + EPSv);
        __nv_bfloat16 hb[4], lb[4];
#pragma unroll
        for (int j = 0; j < 4; j++) {
            float o = acc[i][j] * z;
            hb[j] = __float2bfloat16(o);
            lb[j] = __float2bfloat16(o - __bfloat162float(hb[j]));
        }
        uint32_t sw = sw128((uint32_t)((m0 + i) * 128 + n0 * 2));
        uint2 hv = {pack_bf16x2(hb[0], hb[1]), pack_bf16x2(hb[2], hb[3])};
        uint2 lv = {pack_bf16x2(lb[0], lb[1]), pack_bf16x2(lb[2], lb[3])};
        *(uint2*)(g_at_hi + toff + sw) = hv;
        *(uint2*)(g_at_lo + toff + sw) = lv;
    }
}

// ---------------------------------------------------------------------------
// Launch
// ---------------------------------------------------------------------------
extern "C" void kernel_launch(void* const* d_in, const int* in_sizes, int n_in,
                              void* d_out, int out_size)
{
    const float* x  = (const float*)d_in[0];
    const float* Wq = (const float*)d_in[1];
    const float* bq = (const float*)d_in[2];
    const float* Wk = (const float*)d_in[3];
    const float* bk = (const float*)d_in[4];
    const float* Wv = (const float*)d_in[5];
    const float* bv = (const float*)d_in[6];
    const float* Wo = (const float*)d_in[7];
    const float* bo = (const float*)d_in[8];
    float* out = (float*)d_out;

    float *qp, *kp, *vp;
    unsigned char *xh, *xl, *ath, *atl, *wh, *wl;
    cudaGetSymbolAddress((void**)&qp,  g_q);
    cudaGetSymbolAddress((void**)&kp,  g_k);
    cudaGetSymbolAddress((void**)&vp,  g_v);
    cudaGetSymbolAddress((void**)&xh,  g_xt_hi);
    cudaGetSymbolAddress((void**)&xl,  g_xt_lo);
    cudaGetSymbolAddress((void**)&ath, g_at_hi);
    cudaGetSymbolAddress((void**)&atl, g_at_lo);
    cudaGetSymbolAddress((void**)&wh,  g_w_hi);
    cudaGetSymbolAddress((void**)&wl,  g_w_lo);
    const size_t WSZ = (size_t)Ev * Ev * 2;

    cudaFuncSetAttribute(gemm_mma_kernel<0>, cudaFuncAttributeMaxDynamicSharedMemorySize, SMEM_GEMM);
    cudaFuncSetAttribute(gemm_mma_kernel<1>, cudaFuncAttributeMaxDynamicSharedMemorySize, SMEM_GEMM);

    // 0) zero accumulators (graph replays)
    zero_acc_kernel<<<(Bv * Hv * Dv * Dv + 255) / 256, 256>>>();

    // 1) pack inputs: x -> hi/lo tiles, weights -> transposed hi/lo tiles
    packA_kernel<<<dim3(NCHUNK, Mv / 128), 256>>>(x, xh, xl);
    packB_kernel<<<dim3(NCHUNK, 4), 256>>>(Wq, wh + 0 * WSZ, wl + 0 * WSZ);
    packB_kernel<<<dim3(NCHUNK, 4), 256>>>(Wk, wh + 1 * WSZ, wl + 1 * WSZ);
    packB_kernel<<<dim3(NCHUNK, 4), 256>>>(Wv, wh + 2 * WSZ, wl + 2 * WSZ);
    packB_kernel<<<dim3(NCHUNK, 4), 256>>>(Wo, wh + 3 * WSZ, wl + 3 * WSZ);

    // 2) projections on mma.sync tensor cores (feature map fused into q,k)
    dim3 gg(Ev / 128, Mv / 128);   // (4, 256)
    gemm_mma_kernel<1><<<gg, 256, SMEM_GEMM>>>(xh, xl, wh + 0 * WSZ, wl + 0 * WSZ, bq, qp);
    gemm_mma_kernel<1><<<gg, 256, SMEM_GEMM>>>(xh, xl, wh + 1 * WSZ, wl + 1 * WSZ, bk, kp);
    gemm_mma_kernel<0><<<gg, 256, SMEM_GEMM>>>(xh, xl, wh + 2 * WSZ, wl + 2 * WSZ, bv, vp);

    // 3) KV outer-product reduction + ksum
    kvsum_kernel<<<dim3(8, Bv * Hv), 256>>>();

    // 4) attention apply -> packed hi/lo tiles (no fp32 round-trip)
    attn_kernel<<<dim3(Bv * Hv, Sv / 128), 256>>>();

    // 5) output projection -> d_out
    gemm_mma_kernel<0><<<gg, 256, SMEM_GEMM>>>(ath, atl, wh + 3 * WSZ, wl + 3 * WSZ, bo, out);
}